// round 13
// baseline (speedup 1.0000x reference)
#include <cuda_runtime.h>
#include <cuda_bf16.h>
#include <cstdint>

#define BB 8
#define MM 4096
#define EE 1024
#define DD 128
#define NCAT 64

#define KCH 64
#define NKC (MM / KCH)          // 64
#define NKH 2
#define NCHUNK (NKC / NKH)      // 32
#define NSPLIT 2                // bf16 splits of feats (hi+lo)
#define A_TILE_BYTES (128 * KCH * 2)        // 16384 (bf16 A tile)
#define B_TILE_BYTES (DD * KCH * 2)         // 16384 per split
#define INC_PITCH_B 512                     // fp32 inc row (128 floats)
#define INC_STAGE_B (KCH * INC_PITCH_B)     // 32768
#define STAGE_BYTES (INC_STAGE_B + NSPLIT * B_TILE_BYTES)   // 65536
#define ABUF_OFF (3 * STAGE_BYTES)                          // 196608
#define DYN_SMEM (ABUF_OFF + 2 * A_TILE_BYTES)              // 229376

#define RG_ROWS 64
#define NRGB (BB * EE / RG_ROWS)  // 128 rowgemm blocks

__device__ __align__(128) char  g_Bs[(size_t)BB * NKC * NSPLIT * B_TILE_BYTES];
__device__ __align__(128) float g_aggp[NKH * BB * EE * DD];   // split-K halves
__device__ float g_Wt_att[DD * DD];
__device__ float g_Wt_proj[DD * DD];
__device__ float g_esc[BB * EE * DD];        // holds w = exp(edge_scores)
__device__ float g_colpart[NRGB * DD];       // per-rowgemm0-block column partials
__device__ float g_poolpart[NRGB * DD];      // per-rowgemm1-block pooled numerators
__device__ float g_poolden[NRGB];            // per-rowgemm1-block pooled denominators

__device__ __forceinline__ uint32_t smem_u32(const void* p) {
    uint32_t a;
    asm("{ .reg .u64 t; cvta.to.shared.u64 t, %1; cvt.u32.u64 %0, t; }" : "=r"(a) : "l"(p));
    return a;
}
#define SWZ128(off) ((off) ^ (((off) >> 3) & 0x70))

__device__ __forceinline__ void cpasync16(uint32_t s, const void* g) {
    asm volatile("cp.async.cg.shared.global [%0], [%1], 16;" :: "r"(s), "l"(g));
}
__device__ __forceinline__ void ldsm_x4(uint32_t& r0, uint32_t& r1, uint32_t& r2, uint32_t& r3,
                                        uint32_t addr) {
    asm volatile("ldmatrix.sync.aligned.m8n8.x4.shared.b16 {%0,%1,%2,%3}, [%4];"
                 : "=r"(r0), "=r"(r1), "=r"(r2), "=r"(r3) : "r"(addr));
}
__device__ __forceinline__ void mma16816(float* c, uint32_t a0, uint32_t a1, uint32_t a2,
                                         uint32_t a3, uint32_t b0, uint32_t b1) {
    asm volatile(
        "mma.sync.aligned.m16n8k16.row.col.f32.bf16.bf16.f32 "
        "{%0,%1,%2,%3}, {%4,%5,%6,%7}, {%8,%9}, {%0,%1,%2,%3};"
        : "+f"(c[0]), "+f"(c[1]), "+f"(c[2]), "+f"(c[3])
        : "r"(a0), "r"(a1), "r"(a2), "r"(a3), "r"(b0), "r"(b1));
}

// ---- K1: feats -> 2 bf16 splits, [d=128][m=64] swizzled; + weight transposes ----
__global__ __launch_bounds__(256) void conv_feats(const float* __restrict__ feats,
                                                  const float* __restrict__ Wa,
                                                  const float* __restrict__ Wp) {
    int tid = threadIdx.x;
    int kc = blockIdx.x, b = blockIdx.y;
    if (b == BB) {               // transpose duty: block kc handles rows 2kc, 2kc+1
        int m = tid >> 7, j = tid & 127;
        int k = kc * 2 + m;
        g_Wt_att[k * DD + j] = Wa[j * DD + k];
        g_Wt_proj[k * DD + j] = Wp[j * DD + k];
        return;
    }
    __shared__ float s[64 * 129];
    const float* src = feats + ((size_t)b * MM + kc * 64) * DD;
#pragma unroll
    for (int it = 0; it < 8; it++) {
        int idx = tid + it * 256;
        int row = idx >> 5, c4 = idx & 31;
        float4 v = *(const float4*)(src + (size_t)row * DD + c4 * 4);
        s[row * 129 + c4 * 4 + 0] = v.x; s[row * 129 + c4 * 4 + 1] = v.y;
        s[row * 129 + c4 * 4 + 2] = v.z; s[row * 129 + c4 * 4 + 3] = v.w;
    }
    __syncthreads();
    char* dst = g_Bs + ((size_t)(b * NKC + kc) * NSPLIT) * B_TILE_BYTES;
#pragma unroll
    for (int it = 0; it < 4; it++) {
        int cid = tid + it * 256;
        int drow = cid >> 3, m16 = cid & 7;
        uint32_t ph[4], pl[4];
#pragma unroll
        for (int q = 0; q < 4; q++) {
            float h[2], l[2];
#pragma unroll
            for (int u = 0; u < 2; u++) {
                float x = s[(m16 * 8 + 2 * q + u) * 129 + drow];
                h[u] = __bfloat162float(__float2bfloat16_rn(x));
                l[u] = x - h[u];
            }
            asm("cvt.rn.bf16x2.f32 %0, %1, %2;" : "=r"(ph[q]) : "f"(h[1]), "f"(h[0]));
            asm("cvt.rn.bf16x2.f32 %0, %1, %2;" : "=r"(pl[q]) : "f"(l[1]), "f"(l[0]));
        }
        uint32_t off = SWZ128((uint32_t)(drow * 128 + m16 * 16));
        *(uint4*)(dst + off)                = make_uint4(ph[0], ph[1], ph[2], ph[3]);
        *(uint4*)(dst + B_TILE_BYTES + off) = make_uint4(pl[0], pl[1], pl[2], pl[3]);
    }
}

// ---- K2: fused inc-convert + ldmatrix/mma.sync bf16 GEMM, 512 threads ----
// 16 warps (4e x 4d), warp tile 32e x 32d: 4 warps/SMSP hide ldsm latency.
__global__ __launch_bounds__(512, 1) void mma_agg_kernel(const float* __restrict__ inc) {
    extern __shared__ __align__(1024) char dsm[];
    uint32_t base = smem_u32(dsm);

    int tid = threadIdx.x, lane = tid & 31, wid = tid >> 5;
    int warp_e = wid & 3, warp_d = wid >> 2;
    int et = blockIdx.x, b = blockIdx.y, kh = blockIdx.z;

    const float* incB = inc + ((size_t)b * MM) * EE + et * 128;
    const char* gB = g_Bs + ((size_t)b * NKC * NSPLIT) * B_TILE_BYTES;
    int kc0 = kh * NCHUNK;

    auto stage_copy = [&](int st, int kc) {
        uint32_t sdst = base + st * STAGE_BYTES;
        const float* aF = incB + (size_t)(kc * KCH) * EE;
#pragma unroll
        for (int k = 0; k < 4; k++) {              // 64 rows x 512B fp32 inc
            int idx = tid + k * 512;
            int m = idx >> 5, c16 = idx & 31;
            cpasync16(sdst + m * INC_PITCH_B + c16 * 16, aF + (size_t)m * EE + c16 * 4);
        }
        const char* bb = gB + (size_t)kc * NSPLIT * B_TILE_BYTES;
#pragma unroll
        for (int k = 0; k < 4; k++) {              // 32KB bf16 B
            int off = (tid + k * 512) * 16;
            cpasync16(sdst + INC_STAGE_B + off, bb + off);
        }
        asm volatile("cp.async.commit_group;" ::: "memory");
    };

    // convert fp32 inc slab of chunk c -> bf16 A tile [e][m] swizzled, buffer c&1
    auto convert = [&](int c) {
        const float* sf = (const float*)(dsm + (c % 3) * STAGE_BYTES);
        char* ad = dsm + ABUF_OFF + (c & 1) * A_TILE_BYTES;
#pragma unroll
        for (int rep = 0; rep < 2; rep++) {
            int cid = tid + rep * 512;
            int erow = cid & 127, mb = cid >> 7;     // 128 e-rows x 8 m-blocks
            float f[8];
#pragma unroll
            for (int q = 0; q < 8; q++)
                f[q] = sf[(mb * 8 + q) * (INC_PITCH_B / 4) + erow];
            uint32_t p[4];
#pragma unroll
            for (int q = 0; q < 4; q++)
                asm("cvt.rn.bf16x2.f32 %0, %1, %2;" : "=r"(p[q]) : "f"(f[2 * q + 1]), "f"(f[2 * q]));
            uint32_t off = SWZ128((uint32_t)(erow * 128 + mb * 16));
            *(uint4*)(ad + off) = make_uint4(p[0], p[1], p[2], p[3]);
        }
    };

    float acc[2][4][4];
#pragma unroll
    for (int i = 0; i < 2; i++)
#pragma unroll
        for (int j = 0; j < 4; j++)
#pragma unroll
            for (int c = 0; c < 4; c++) acc[i][j][c] = 0.f;

    int a_row = warp_e * 32 + (lane & 15);
    int a_kb  = (lane >> 4) << 4;
    int b_row = warp_d * 32 + (lane & 7) + ((lane >> 4) << 3);
    int b_kb  = (lane & 8) * 2;

    stage_copy(0, kc0);
    stage_copy(1, kc0 + 1);
    stage_copy(2, kc0 + 2);
    asm volatile("cp.async.wait_group 2;" ::: "memory");   // chunk kc0 arrived
    __syncthreads();
    convert(0);                                            // A0 (visible after iter-0 sync)

    for (int i = 0; i < NCHUNK; i++) {
        if (i + 2 < NCHUNK)      { asm volatile("cp.async.wait_group 1;" ::: "memory"); }
        else if (i + 1 < NCHUNK) { asm volatile("cp.async.wait_group 0;" ::: "memory"); }
        __syncthreads();

        if (i + 1 < NCHUNK) convert(i + 1);   // interleaves with mma below

        uint32_t sA = base + ABUF_OFF + (i & 1) * A_TILE_BYTES;
        uint32_t sB = base + (i % 3) * STAGE_BYTES + INC_STAGE_B;
#pragma unroll
        for (int t = 0; t < 4; t++) {
            uint32_t a[2][4];
#pragma unroll
            for (int ei = 0; ei < 2; ei++) {
                uint32_t off = (uint32_t)((a_row + ei * 16) * 128 + a_kb + t * 32);
                ldsm_x4(a[ei][0], a[ei][1], a[ei][2], a[ei][3], sA + SWZ128(off));
            }
#pragma unroll
            for (int s = 0; s < NSPLIT; s++) {
#pragma unroll
                for (int j = 0; j < 2; j++) {
                    uint32_t b0, b1, b2, b3;
                    uint32_t off = (uint32_t)((b_row + j * 16) * 128 + b_kb + t * 32);
                    ldsm_x4(b0, b1, b2, b3, sB + s * B_TILE_BYTES + SWZ128(off));
#pragma unroll
                    for (int ei = 0; ei < 2; ei++) {
                        mma16816(acc[ei][j * 2 + 0], a[ei][0], a[ei][1], a[ei][2], a[ei][3], b0, b1);
                        mma16816(acc[ei][j * 2 + 1], a[ei][0], a[ei][1], a[ei][2], a[ei][3], b2, b3);
                    }
                }
            }
        }
        __syncthreads();   // A[(i+1)&1] written & stage[i%3] drained
        if (i + 3 < NCHUNK) stage_copy(i % 3, kc0 + i + 3);
    }

    float* gout = g_aggp + (((size_t)kh * BB + b) * EE + et * 128) * DD;
    int gr = lane >> 2, gc = (lane & 3) * 2;
#pragma unroll
    for (int ei = 0; ei < 2; ei++) {
#pragma unroll
        for (int jj = 0; jj < 4; jj++) {
            int e_ = warp_e * 32 + ei * 16 + gr;
            int d_ = warp_d * 32 + jj * 8 + gc;
            *(float2*)(gout + (size_t)e_ * DD + d_) = make_float2(acc[ei][jj][0], acc[ei][jj][1]);
            *(float2*)(gout + (size_t)(e_ + 8) * DD + d_) = make_float2(acc[ei][jj][2], acc[ei][jj][3]);
        }
    }
}

// ---- rowgemm on agg = aggp0+aggp1, 64-row tiles, 512 threads ----
// PHASE 0: esc GEMM (Wt_att) -> stores w=exp(esc) + per-block column partials
// PHASE 1: edgefeat GEMM on (agg * w * invcolsum) (Wt_proj), fused pooling.
template <int PHASE>
__global__ __launch_bounds__(512) void rowgemm(const float* __restrict__ attw) {
    __shared__ float WtS[32 * 128];
    __shared__ float fsh[RG_ROWS * 33];
    __shared__ __align__(16) float sICS[128];
    __shared__ float redc[16 * 128];
    __shared__ float sden[16];
    const float* __restrict__ X0 = g_aggp;
    const float* __restrict__ X1 = g_aggp + (size_t)BB * EE * DD;
    const float* __restrict__ Wt = (PHASE == 0) ? g_Wt_att : g_Wt_proj;

    int tid = threadIdx.x;
    int tx = tid & 31, ty = tid >> 5;       // ty 0..15, 4 rows each
    int row0 = blockIdx.x * RG_ROWS;
    int bb = blockIdx.x >> 4;               // 16 blocks per batch

    if (PHASE == 1) {   // finish column-softmax denominators -> inverse, in smem
        if (tid < 128) {
            float t = 0.f;
#pragma unroll
            for (int blk = 0; blk < 16; blk++) t += g_colpart[(bb * 16 + blk) * 128 + tid];
            sICS[tid] = 1.f / t;
        }
        __syncthreads();
    }

    float acc[4][4];
#pragma unroll
    for (int i = 0; i < 4; i++)
#pragma unroll
        for (int c = 0; c < 4; c++) acc[i][c] = 0.f;

    for (int kc = 0; kc < DD; kc += 32) {
#pragma unroll
        for (int i = 0; i < 2; i++) {
            int slot = tid + i * 512;
            int k = slot >> 5, j4 = slot & 31;
            *reinterpret_cast<float4*>(&WtS[k * 128 + j4 * 4]) =
                *reinterpret_cast<const float4*>(&Wt[(kc + k) * DD + j4 * 4]);
        }
        {
            int r = tid >> 3, kq = tid & 7;
            size_t idx = (size_t)(row0 + r) * DD + kc + kq * 4;
            float4 v0 = *reinterpret_cast<const float4*>(&X0[idx]);
            float4 v1 = *reinterpret_cast<const float4*>(&X1[idx]);
            float fx = v0.x + v1.x, fy = v0.y + v1.y, fz = v0.z + v1.z, fw = v0.w + v1.w;
            if (PHASE == 1) {
                float4 w = *reinterpret_cast<const float4*>(&g_esc[idx]);
                float4 ic = *reinterpret_cast<const float4*>(&sICS[kc + kq * 4]);
                fx *= w.x * ic.x; fy *= w.y * ic.y; fz *= w.z * ic.z; fw *= w.w * ic.w;
            }
            fsh[r * 33 + kq * 4 + 0] = fx; fsh[r * 33 + kq * 4 + 1] = fy;
            fsh[r * 33 + kq * 4 + 2] = fz; fsh[r * 33 + kq * 4 + 3] = fw;
        }
        __syncthreads();
#pragma unroll
        for (int k = 0; k < 32; k++) {
            float4 w4 = *reinterpret_cast<const float4*>(&WtS[k * 128 + tx * 4]);
#pragma unroll
            for (int i = 0; i < 4; i++) {
                float f = fsh[(ty * 4 + i) * 33 + k];
                acc[i][0] = fmaf(f, w4.x, acc[i][0]);
                acc[i][1] = fmaf(f, w4.y, acc[i][1]);
                acc[i][2] = fmaf(f, w4.z, acc[i][2]);
                acc[i][3] = fmaf(f, w4.w, acc[i][3]);
            }
        }
        __syncthreads();
    }

    if (PHASE == 0) {
        float colp[4] = {0.f, 0.f, 0.f, 0.f};
#pragma unroll
        for (int i = 0; i < 4; i++) {
            int r = row0 + ty * 4 + i;
#pragma unroll
            for (int c = 0; c < 4; c++) {
                float w = __expf(acc[i][c]);
                acc[i][c] = w;
                colp[c] += w;
            }
            *reinterpret_cast<float4*>(&g_esc[(size_t)r * DD + tx * 4]) =
                make_float4(acc[i][0], acc[i][1], acc[i][2], acc[i][3]);
        }
        *reinterpret_cast<float4*>(&redc[ty * 128 + tx * 4]) =
            make_float4(colp[0], colp[1], colp[2], colp[3]);
        __syncthreads();
        if (ty == 0) {
#pragma unroll
            for (int c = 0; c < 4; c++) {
                float s = 0.f;
#pragma unroll
                for (int t = 0; t < 16; t++) s += redc[t * 128 + tx * 4 + c];
                g_colpart[blockIdx.x * 128 + tx * 4 + c] = s;
            }
        }
    } else {
        float4 aw = *reinterpret_cast<const float4*>(&attw[tx * 4]);
        float pacc[4] = {0.f, 0.f, 0.f, 0.f};
        float dacc = 0.f;
#pragma unroll
        for (int i = 0; i < 4; i++) {
            float4 v = make_float4(acc[i][0], acc[i][1], acc[i][2], acc[i][3]);
            float p = v.x * aw.x + v.y * aw.y + v.z * aw.z + v.w * aw.w;
#pragma unroll
            for (int off = 16; off > 0; off >>= 1)
                p += __shfl_xor_sync(0xffffffffu, p, off);
            float wv = __expf(p);
            pacc[0] = fmaf(v.x, wv, pacc[0]); pacc[1] = fmaf(v.y, wv, pacc[1]);
            pacc[2] = fmaf(v.z, wv, pacc[2]); pacc[3] = fmaf(v.w, wv, pacc[3]);
            dacc += wv;
        }
        *reinterpret_cast<float4*>(&redc[ty * 128 + tx * 4]) =
            make_float4(pacc[0], pacc[1], pacc[2], pacc[3]);
        if (tx == 0) sden[ty] = dacc;
        __syncthreads();
        if (ty == 0) {
#pragma unroll
            for (int c = 0; c < 4; c++) {
                float s = 0.f;
#pragma unroll
                for (int t = 0; t < 16; t++) s += redc[t * 128 + tx * 4 + c];
                g_poolpart[blockIdx.x * 128 + tx * 4 + c] = s;
            }
        }
        if (tid == 0) {
            float s = 0.f;
#pragma unroll
            for (int t = 0; t < 16; t++) s += sden[t];
            g_poolden[blockIdx.x] = s;
        }
    }
}

// ---- K5: pooled = numer/S; out = pooled@ec_proj^T + b; logits = out@fc^T + fc_b ----
__global__ __launch_bounds__(128) void pool_head(const float* __restrict__ ec_proj_w,
                                                 const float* __restrict__ ec_proj_b,
                                                 const float* __restrict__ fc_w,
                                                 const float* __restrict__ fc_b,
                                                 float* __restrict__ out) {
    int b = blockIdx.x, d = threadIdx.x;
    __shared__ float p[DD];
    __shared__ float o[DD];
    float n = 0.f, S = 0.f;
#pragma unroll
    for (int blk = 0; blk < 16; blk++) {
        n += g_poolpart[(b * 16 + blk) * 128 + d];
        S += g_poolden[b * 16 + blk];
    }
    p[d] = n / S;
    __syncthreads();
    float acc = ec_proj_b[d];
#pragma unroll 4
    for (int k = 0; k < DD; k++) acc = fmaf(p[k], ec_proj_w[d * DD + k], acc);
    o[d] = acc;
    __syncthreads();
    if (d < NCAT) {
        float l = fc_b[d];
#pragma unroll 4
        for (int k = 0; k < DD; k++) l = fmaf(o[k], fc_w[d * DD + k], l);
        out[b * NCAT + d] = l;
    }
}

// ---- launch ----
extern "C" void kernel_launch(void* const* d_in, const int* in_sizes, int n_in,
                              void* d_out, int out_size) {
    const float* node_feats = (const float*)d_in[0];
    const float* inc_mat    = (const float*)d_in[1];
    const float* W_att      = (const float*)d_in[2];
    const float* W_proj     = (const float*)d_in[3];
    const float* ec_att_w   = (const float*)d_in[4];
    const float* ec_proj_w  = (const float*)d_in[5];
    const float* ec_proj_b  = (const float*)d_in[6];
    const float* fc_w       = (const float*)d_in[7];
    const float* fc_b       = (const float*)d_in[8];
    float* out = (float*)d_out;

    cudaFuncSetAttribute(mma_agg_kernel, cudaFuncAttributeMaxDynamicSharedMemorySize, DYN_SMEM);

    conv_feats<<<dim3(NKC, BB + 1), 256>>>(node_feats, W_att, W_proj);
    mma_agg_kernel<<<dim3(8, BB, NKH), 512, DYN_SMEM>>>(inc_mat);
    rowgemm<0><<<NRGB, 512>>>(nullptr);               // w=exp(esc) + column partials
    rowgemm<1><<<NRGB, 512>>>(ec_att_w);              // fused inv-colsum + pooling
    pool_head<<<BB, 128>>>(ec_proj_w, ec_proj_b, fc_w, fc_b, out);
}

// round 15
// speedup vs baseline: 1.0135x; 1.0135x over previous
#include <cuda_runtime.h>
#include <cuda_bf16.h>
#include <cstdint>

#define BB 8
#define MM 4096
#define EE 1024
#define DD 128
#define NCAT 64

#define KCH 64
#define NKC (MM / KCH)          // 64
#define NKH 2
#define NCHUNK (NKC / NKH)      // 32
#define NSPLIT 2                // bf16 splits of feats (hi+lo)
#define A_TILE_BYTES (128 * KCH * 2)        // 16384 (bf16 A tile)
#define B_TILE_BYTES (DD * KCH * 2)         // 16384 per split
#define INC_PITCH_B 512                     // fp32 inc row (128 floats)
#define INC_STAGE_B (KCH * INC_PITCH_B)     // 32768
#define STAGE_BYTES (INC_STAGE_B + NSPLIT * B_TILE_BYTES)   // 65536
#define ABUF_OFF (3 * STAGE_BYTES)                          // 196608
#define DYN_SMEM (ABUF_OFF + 2 * A_TILE_BYTES)              // 229376

#define RG_ROWS 64
#define NRGB (BB * EE / RG_ROWS)  // 128 rowgemm blocks

__device__ __align__(128) char  g_Bs[(size_t)BB * NKC * NSPLIT * B_TILE_BYTES];
__device__ __align__(128) float g_aggp[NKH * BB * EE * DD];   // split-K halves
__device__ float g_Wt_att[DD * DD];
__device__ float g_Wt_proj[DD * DD];
__device__ float g_esc[BB * EE * DD];        // holds w = exp(edge_scores)
__device__ float g_colpart[NRGB * DD];       // per-rowgemm0-block column partials
__device__ float g_poolpart[NRGB * DD];      // per-rowgemm1-block pooled numerators
__device__ float g_poolden[NRGB];            // per-rowgemm1-block pooled denominators

__device__ __forceinline__ uint32_t smem_u32(const void* p) {
    uint32_t a;
    asm("{ .reg .u64 t; cvta.to.shared.u64 t, %1; cvt.u32.u64 %0, t; }" : "=r"(a) : "l"(p));
    return a;
}
#define SWZ128(off) ((off) ^ (((off) >> 3) & 0x70))

__device__ __forceinline__ void cpasync16(uint32_t s, const void* g) {
    asm volatile("cp.async.cg.shared.global [%0], [%1], 16;" :: "r"(s), "l"(g));
}
__device__ __forceinline__ void ldsm_x4(uint32_t& r0, uint32_t& r1, uint32_t& r2, uint32_t& r3,
                                        uint32_t addr) {
    asm volatile("ldmatrix.sync.aligned.m8n8.x4.shared.b16 {%0,%1,%2,%3}, [%4];"
                 : "=r"(r0), "=r"(r1), "=r"(r2), "=r"(r3) : "r"(addr));
}
__device__ __forceinline__ void mma16816(float* c, uint32_t a0, uint32_t a1, uint32_t a2,
                                         uint32_t a3, uint32_t b0, uint32_t b1) {
    asm volatile(
        "mma.sync.aligned.m16n8k16.row.col.f32.bf16.bf16.f32 "
        "{%0,%1,%2,%3}, {%4,%5,%6,%7}, {%8,%9}, {%0,%1,%2,%3};"
        : "+f"(c[0]), "+f"(c[1]), "+f"(c[2]), "+f"(c[3])
        : "r"(a0), "r"(a1), "r"(a2), "r"(a3), "r"(b0), "r"(b1));
}

// ---- K1: feats -> 2 bf16 splits, [d=128][m=64] swizzled; + weight transposes ----
__global__ __launch_bounds__(256) void conv_feats(const float* __restrict__ feats,
                                                  const float* __restrict__ Wa,
                                                  const float* __restrict__ Wp) {
    int tid = threadIdx.x;
    int kc = blockIdx.x, b = blockIdx.y;
    if (b == BB) {               // transpose duty: block kc handles rows 2kc, 2kc+1
        int m = tid >> 7, j = tid & 127;
        int k = kc * 2 + m;
        g_Wt_att[k * DD + j] = Wa[j * DD + k];
        g_Wt_proj[k * DD + j] = Wp[j * DD + k];
        return;
    }
    __shared__ float s[64 * 129];
    const float* src = feats + ((size_t)b * MM + kc * 64) * DD;
#pragma unroll
    for (int it = 0; it < 8; it++) {
        int idx = tid + it * 256;
        int row = idx >> 5, c4 = idx & 31;
        float4 v = *(const float4*)(src + (size_t)row * DD + c4 * 4);
        s[row * 129 + c4 * 4 + 0] = v.x; s[row * 129 + c4 * 4 + 1] = v.y;
        s[row * 129 + c4 * 4 + 2] = v.z; s[row * 129 + c4 * 4 + 3] = v.w;
    }
    __syncthreads();
    char* dst = g_Bs + ((size_t)(b * NKC + kc) * NSPLIT) * B_TILE_BYTES;
#pragma unroll
    for (int it = 0; it < 4; it++) {
        int cid = tid + it * 256;
        int drow = cid >> 3, m16 = cid & 7;
        uint32_t ph[4], pl[4];
#pragma unroll
        for (int q = 0; q < 4; q++) {
            float h[2], l[2];
#pragma unroll
            for (int u = 0; u < 2; u++) {
                float x = s[(m16 * 8 + 2 * q + u) * 129 + drow];
                h[u] = __bfloat162float(__float2bfloat16_rn(x));
                l[u] = x - h[u];
            }
            asm("cvt.rn.bf16x2.f32 %0, %1, %2;" : "=r"(ph[q]) : "f"(h[1]), "f"(h[0]));
            asm("cvt.rn.bf16x2.f32 %0, %1, %2;" : "=r"(pl[q]) : "f"(l[1]), "f"(l[0]));
        }
        uint32_t off = SWZ128((uint32_t)(drow * 128 + m16 * 16));
        *(uint4*)(dst + off)                = make_uint4(ph[0], ph[1], ph[2], ph[3]);
        *(uint4*)(dst + B_TILE_BYTES + off) = make_uint4(pl[0], pl[1], pl[2], pl[3]);
    }
}

// ---- K2: fused inc-convert + ldmatrix/mma.sync bf16 GEMM (R12 traffic-optimal) ----
// 8 warps (2e x 4d), warp tile 64e x 32d; 3 raw stages + double-buffered A tile;
// convert(i+1) interleaves with mma(i).
__global__ __launch_bounds__(256, 1) void mma_agg_kernel(const float* __restrict__ inc) {
    extern __shared__ __align__(1024) char dsm[];
    uint32_t base = smem_u32(dsm);

    int tid = threadIdx.x, lane = tid & 31, wid = tid >> 5;
    int warp_e = wid & 1, warp_d = wid >> 1;
    int et = blockIdx.x, b = blockIdx.y, kh = blockIdx.z;

    const float* incB = inc + ((size_t)b * MM) * EE + et * 128;
    const char* gB = g_Bs + ((size_t)b * NKC * NSPLIT) * B_TILE_BYTES;
    int kc0 = kh * NCHUNK;

    auto stage_copy = [&](int st, int kc) {
        uint32_t sdst = base + st * STAGE_BYTES;
        const float* aF = incB + (size_t)(kc * KCH) * EE;
#pragma unroll
        for (int k = 0; k < 8; k++) {
            int idx = tid + k * 256;
            int m = idx >> 5, c16 = idx & 31;
            cpasync16(sdst + m * INC_PITCH_B + c16 * 16, aF + (size_t)m * EE + c16 * 4);
        }
        const char* bb = gB + (size_t)kc * NSPLIT * B_TILE_BYTES;
#pragma unroll
        for (int k = 0; k < 8; k++) {
            int off = (tid + k * 256) * 16;
            cpasync16(sdst + INC_STAGE_B + off, bb + off);
        }
        asm volatile("cp.async.commit_group;" ::: "memory");
    };

    auto convert = [&](int c) {
        const float* sf = (const float*)(dsm + (c % 3) * STAGE_BYTES);
        char* ad = dsm + ABUF_OFF + (c & 1) * A_TILE_BYTES;
#pragma unroll
        for (int rep = 0; rep < 4; rep++) {
            int cid = tid + rep * 256;
            int erow = cid & 127, mb = cid >> 7;
            float f[8];
#pragma unroll
            for (int q = 0; q < 8; q++)
                f[q] = sf[(mb * 8 + q) * (INC_PITCH_B / 4) + erow];
            uint32_t p[4];
#pragma unroll
            for (int q = 0; q < 4; q++)
                asm("cvt.rn.bf16x2.f32 %0, %1, %2;" : "=r"(p[q]) : "f"(f[2 * q + 1]), "f"(f[2 * q]));
            uint32_t off = SWZ128((uint32_t)(erow * 128 + mb * 16));
            *(uint4*)(ad + off) = make_uint4(p[0], p[1], p[2], p[3]);
        }
    };

    float acc[4][4][4];
#pragma unroll
    for (int i = 0; i < 4; i++)
#pragma unroll
        for (int j = 0; j < 4; j++)
#pragma unroll
            for (int c = 0; c < 4; c++) acc[i][j][c] = 0.f;

    int a_row = warp_e * 64 + (lane & 15);
    int a_kb  = (lane >> 4) << 4;
    int b_row = warp_d * 32 + (lane & 7) + ((lane >> 4) << 3);
    int b_kb  = (lane & 8) * 2;

    stage_copy(0, kc0);
    stage_copy(1, kc0 + 1);
    stage_copy(2, kc0 + 2);
    asm volatile("cp.async.wait_group 2;" ::: "memory");
    __syncthreads();
    convert(0);

    for (int i = 0; i < NCHUNK; i++) {
        if (i + 2 < NCHUNK)      { asm volatile("cp.async.wait_group 1;" ::: "memory"); }
        else if (i + 1 < NCHUNK) { asm volatile("cp.async.wait_group 0;" ::: "memory"); }
        __syncthreads();

        if (i + 1 < NCHUNK) convert(i + 1);

        uint32_t sA = base + ABUF_OFF + (i & 1) * A_TILE_BYTES;
        uint32_t sB = base + (i % 3) * STAGE_BYTES + INC_STAGE_B;
#pragma unroll
        for (int t = 0; t < 4; t++) {
            uint32_t a[4][4];
#pragma unroll
            for (int ei = 0; ei < 4; ei++) {
                uint32_t off = (uint32_t)((a_row + ei * 16) * 128 + a_kb + t * 32);
                ldsm_x4(a[ei][0], a[ei][1], a[ei][2], a[ei][3], sA + SWZ128(off));
            }
#pragma unroll
            for (int s = 0; s < NSPLIT; s++) {
#pragma unroll
                for (int j = 0; j < 2; j++) {
                    uint32_t b0, b1, b2, b3;
                    uint32_t off = (uint32_t)((b_row + j * 16) * 128 + b_kb + t * 32);
                    ldsm_x4(b0, b1, b2, b3, sB + s * B_TILE_BYTES + SWZ128(off));
#pragma unroll
                    for (int ei = 0; ei < 4; ei++) {
                        mma16816(acc[ei][j * 2 + 0], a[ei][0], a[ei][1], a[ei][2], a[ei][3], b0, b1);
                        mma16816(acc[ei][j * 2 + 1], a[ei][0], a[ei][1], a[ei][2], a[ei][3], b2, b3);
                    }
                }
            }
        }
        __syncthreads();
        if (i + 3 < NCHUNK) stage_copy(i % 3, kc0 + i + 3);
    }

    float* gout = g_aggp + (((size_t)kh * BB + b) * EE + et * 128) * DD;
    int gr = lane >> 2, gc = (lane & 3) * 2;
#pragma unroll
    for (int ei = 0; ei < 4; ei++) {
#pragma unroll
        for (int jj = 0; jj < 4; jj++) {
            int e_ = warp_e * 64 + ei * 16 + gr;
            int d_ = warp_d * 32 + jj * 8 + gc;
            *(float2*)(gout + (size_t)e_ * DD + d_) = make_float2(acc[ei][jj][0], acc[ei][jj][1]);
            *(float2*)(gout + (size_t)(e_ + 8) * DD + d_) = make_float2(acc[ei][jj][2], acc[ei][jj][3]);
        }
    }
}

// ---- rowgemm on agg = aggp0+aggp1, 64-row tiles, 256 threads, float4 X loads ----
// PHASE 0: esc GEMM (Wt_att) -> stores w=exp(esc) + per-block column partials
// PHASE 1: edgefeat GEMM on (agg * w * invcolsum) (Wt_proj), fused pooling.
template <int PHASE>
__global__ __launch_bounds__(256) void rowgemm(const float* __restrict__ attw) {
    __shared__ float WtS[32 * 128];
    __shared__ float fsh[RG_ROWS * 36];     // pitch 36 floats = 144 B (16B-aligned)
    __shared__ __align__(16) float sICS[128];
    __shared__ float redc[8 * 128];
    __shared__ float sden[8];
    const float* __restrict__ X0 = g_aggp;
    const float* __restrict__ X1 = g_aggp + (size_t)BB * EE * DD;
    const float* __restrict__ Wt = (PHASE == 0) ? g_Wt_att : g_Wt_proj;

    int tid = threadIdx.x;
    int tx = tid & 31, ty = tid >> 5;       // ty 0..7, 8 rows each
    int row0 = blockIdx.x * RG_ROWS;
    int bb = blockIdx.x >> 4;               // 16 blocks per batch

    if (PHASE == 1) {   // finish column-softmax denominators -> inverse, in smem
        if (tid < 128) {
            float t = 0.f;
#pragma unroll
            for (int blk = 0; blk < 16; blk++) t += g_colpart[(bb * 16 + blk) * 128 + tid];
            sICS[tid] = 1.f / t;
        }
        __syncthreads();
    }

    float acc[8][4];
#pragma unroll
    for (int i = 0; i < 8; i++)
#pragma unroll
        for (int c = 0; c < 4; c++) acc[i][c] = 0.f;

    for (int kc = 0; kc < DD; kc += 32) {
#pragma unroll
        for (int i = 0; i < 4; i++) {
            int slot = tid + i * 256;
            int k = slot >> 5, j4 = slot & 31;
            *reinterpret_cast<float4*>(&WtS[k * 128 + j4 * 4]) =
                *reinterpret_cast<const float4*>(&Wt[(kc + k) * DD + j4 * 4]);
        }
#pragma unroll
        for (int i = 0; i < 2; i++) {
            int slot = tid + i * 256;
            int r = slot >> 3, kq = slot & 7;
            size_t idx = (size_t)(row0 + r) * DD + kc + kq * 4;
            float4 v0 = *reinterpret_cast<const float4*>(&X0[idx]);
            float4 v1 = *reinterpret_cast<const float4*>(&X1[idx]);
            float4 f = make_float4(v0.x + v1.x, v0.y + v1.y, v0.z + v1.z, v0.w + v1.w);
            if (PHASE == 1) {
                float4 w = *reinterpret_cast<const float4*>(&g_esc[idx]);
                float4 ic = *reinterpret_cast<const float4*>(&sICS[kc + kq * 4]);
                f.x *= w.x * ic.x; f.y *= w.y * ic.y; f.z *= w.z * ic.z; f.w *= w.w * ic.w;
            }
            *reinterpret_cast<float4*>(&fsh[r * 36 + kq * 4]) = f;   // 16B-aligned
        }
        __syncthreads();
#pragma unroll
        for (int kk = 0; kk < 32; kk += 4) {
            float4 f[8];
#pragma unroll
            for (int i = 0; i < 8; i++)     // broadcast LDS.128 (all lanes share ty)
                f[i] = *reinterpret_cast<const float4*>(&fsh[(ty * 8 + i) * 36 + kk]);
#pragma unroll
            for (int q = 0; q < 4; q++) {
                float4 w4 = *reinterpret_cast<const float4*>(&WtS[(kk + q) * 128 + tx * 4]);
                const float fq0 = (&f[0].x)[q];
#pragma unroll
                for (int i = 0; i < 8; i++) {
                    float fv = (q == 0) ? (&f[i].x)[0] : (q == 1) ? (&f[i].x)[1]
                             : (q == 2) ? (&f[i].x)[2] : (&f[i].x)[3];
                    acc[i][0] = fmaf(fv, w4.x, acc[i][0]);
                    acc[i][1] = fmaf(fv, w4.y, acc[i][1]);
                    acc[i][2] = fmaf(fv, w4.z, acc[i][2]);
                    acc[i][3] = fmaf(fv, w4.w, acc[i][3]);
                }
                (void)fq0;
            }
        }
        __syncthreads();
    }

    if (PHASE == 0) {
        float colp[4] = {0.f, 0.f, 0.f, 0.f};
#pragma unroll
        for (int i = 0; i < 8; i++) {
            int r = row0 + ty * 8 + i;
#pragma unroll
            for (int c = 0; c < 4; c++) {
                float w = __expf(acc[i][c]);
                acc[i][c] = w;
                colp[c] += w;
            }
            *reinterpret_cast<float4*>(&g_esc[(size_t)r * DD + tx * 4]) =
                make_float4(acc[i][0], acc[i][1], acc[i][2], acc[i][3]);
        }
        *reinterpret_cast<float4*>(&redc[ty * 128 + tx * 4]) =
            make_float4(colp[0], colp[1], colp[2], colp[3]);
        __syncthreads();
        if (ty == 0) {
#pragma unroll
            for (int c = 0; c < 4; c++) {
                float s = 0.f;
#pragma unroll
                for (int t = 0; t < 8; t++) s += redc[t * 128 + tx * 4 + c];
                g_colpart[blockIdx.x * 128 + tx * 4 + c] = s;
            }
        }
    } else {
        float4 aw = *reinterpret_cast<const float4*>(&attw[tx * 4]);
        float pacc[4] = {0.f, 0.f, 0.f, 0.f};
        float dacc = 0.f;
#pragma unroll
        for (int i = 0; i < 8; i++) {
            float4 v = make_float4(acc[i][0], acc[i][1], acc[i][2], acc[i][3]);
            float p = v.x * aw.x + v.y * aw.y + v.z * aw.z + v.w * aw.w;
#pragma unroll
            for (int off = 16; off > 0; off >>= 1)
                p += __shfl_xor_sync(0xffffffffu, p, off);
            float wv = __expf(p);
            pacc[0] = fmaf(v.x, wv, pacc[0]); pacc[1] = fmaf(v.y, wv, pacc[1]);
            pacc[2] = fmaf(v.z, wv, pacc[2]); pacc[3] = fmaf(v.w, wv, pacc[3]);
            dacc += wv;
        }
        *reinterpret_cast<float4*>(&redc[ty * 128 + tx * 4]) =
            make_float4(pacc[0], pacc[1], pacc[2], pacc[3]);
        if (tx == 0) sden[ty] = dacc;
        __syncthreads();
        if (ty == 0) {
#pragma unroll
            for (int c = 0; c < 4; c++) {
                float s = 0.f;
#pragma unroll
                for (int t = 0; t < 8; t++) s += redc[t * 128 + tx * 4 + c];
                g_poolpart[blockIdx.x * 128 + tx * 4 + c] = s;
            }
        }
        if (tid == 0) {
            float s = 0.f;
#pragma unroll
            for (int t = 0; t < 8; t++) s += sden[t];
            g_poolden[blockIdx.x] = s;
        }
    }
}

// ---- K5: pooled = numer/S; out = pooled@ec_proj^T + b; logits = out@fc^T + fc_b ----
__global__ __launch_bounds__(128) void pool_head(const float* __restrict__ ec_proj_w,
                                                 const float* __restrict__ ec_proj_b,
                                                 const float* __restrict__ fc_w,
                                                 const float* __restrict__ fc_b,
                                                 float* __restrict__ out) {
    int b = blockIdx.x, d = threadIdx.x;
    __shared__ float p[DD];
    __shared__ float o[DD];
    float n = 0.f, S = 0.f;
#pragma unroll
    for (int blk = 0; blk < 16; blk++) {
        n += g_poolpart[(b * 16 + blk) * 128 + d];
        S += g_poolden[b * 16 + blk];
    }
    p[d] = n / S;
    __syncthreads();
    float acc = ec_proj_b[d];
#pragma unroll 4
    for (int k = 0; k < DD; k++) acc = fmaf(p[k], ec_proj_w[d * DD + k], acc);
    o[d] = acc;
    __syncthreads();
    if (d < NCAT) {
        float l = fc_b[d];
#pragma unroll 4
        for (int k = 0; k < DD; k++) l = fmaf(o[k], fc_w[d * DD + k], l);
        out[b * NCAT + d] = l;
    }
}

// ---- launch ----
extern "C" void kernel_launch(void* const* d_in, const int* in_sizes, int n_in,
                              void* d_out, int out_size) {
    const float* node_feats = (const float*)d_in[0];
    const float* inc_mat    = (const float*)d_in[1];
    const float* W_att      = (const float*)d_in[2];
    const float* W_proj     = (const float*)d_in[3];
    const float* ec_att_w   = (const float*)d_in[4];
    const float* ec_proj_w  = (const float*)d_in[5];
    const float* ec_proj_b  = (const float*)d_in[6];
    const float* fc_w       = (const float*)d_in[7];
    const float* fc_b       = (const float*)d_in[8];
    float* out = (float*)d_out;

    cudaFuncSetAttribute(mma_agg_kernel, cudaFuncAttributeMaxDynamicSharedMemorySize, DYN_SMEM);

    conv_feats<<<dim3(NKC, BB + 1), 256>>>(node_feats, W_att, W_proj);
    mma_agg_kernel<<<dim3(8, BB, NKH), 256, DYN_SMEM>>>(inc_mat);
    rowgemm<0><<<NRGB, 256>>>(nullptr);               // w=exp(esc) + column partials
    rowgemm<1><<<NRGB, 256>>>(ec_att_w);              // fused inv-colsum + pooling
    pool_head<<<BB, 128>>>(ec_proj_w, ec_proj_b, fc_w, fc_b, out);
}